// round 15
// baseline (speedup 1.0000x reference)
#include <cuda_runtime.h>
#include <cuda_bf16.h>

// NeuSSampler inverse-CDF importance sampling — v15: v12 minus fat.
// weights [R,128,1] f32, existing_bins [R,129] f32, nears [R,1], fars [R,1]
// -> out [R,65] f32.  One warp per ray.
//
// Unified per-warp smem table: cdf[0..128] at offset 0, bins[0..128] at
// offset 132 floats. Per query, ONE base address serves all four endpoint
// loads via LDS immediate offsets (+0,+4,+528,+532) — no per-query global
// addressing, no prefetch. Owner search: dual 5-probe shfl ladder (shared
// first probe) + SWAR byte-compare boundaries. j=64: owner lane local.

#define S_SAMP 128
#define NB 65
#define HIST_PAD 1e-5f
#define EPS_V 1e-5f
#define WPB 8
#define NTHREADS (WPB * 32)
#define INV_NB (1.0f / 65.0f)
#define FULL 0xffffffffu
#define BOFF 132            // float offset of bin table inside tbl row

__global__ __launch_bounds__(NTHREADS)
void neus_sampler_kernel(const float* __restrict__ weights,
                         const float* __restrict__ ebins,
                         const float* __restrict__ nears,
                         const float* __restrict__ fars,
                         float* __restrict__ out,
                         int R)
{
    __shared__ __align__(16) float tbl_sm[WPB][BOFF + 132];

    const int warp = threadIdx.x >> 5;
    const int lane = threadIdx.x & 31;
    const unsigned ray = blockIdx.x * WPB + warp;
    if (ray >= (unsigned)R) return;

    float* tb = tbl_sm[warp];
    const int k = lane * 4;

    // ---- A0. all global loads up front (max MLP) ----
    const float* ebrow = ebins + ray * 129u;
    const float4 wv = *reinterpret_cast<const float4*>(weights + ray * 128u + k);
    const float b0 = __ldg(ebrow + k);
    const float b1 = __ldg(ebrow + k + 1);
    const float b2 = __ldg(ebrow + k + 2);
    const float b3 = __ldg(ebrow + k + 3);
    const float nearv = __ldg(nears + ray);
    const float farv  = __ldg(fars + ray);

    const float l0 = wv.x;
    const float l1 = l0 + wv.y;
    const float l2 = l1 + wv.z;
    const float l3 = l2 + wv.w;

    // ---- A1. warp inclusive scan over chunk sums ----
    float pre = l3;
    #pragma unroll
    for (int off = 1; off < 32; off <<= 1) {
        float v = __shfl_up_sync(FULL, pre, off);
        if (lane >= off) pre += v;
    }
    const float total_raw = __shfl_sync(FULL, pre, 31);
    const float excl      = pre - l3;

    const float total_wp = total_raw + (float)S_SAMP * HIST_PAD;
    const float padding  = fmaxf(0.0f, EPS_V - total_wp);
    const float inv_wsum = __fdividef(1.0f, total_wp + padding);
    const float step     = HIST_PAD + padding * (1.0f / (float)S_SAMP);

    const float kf = (float)k;
    const float c0 = fmaf(kf,        step, excl     ) * inv_wsum;
    const float c1 = fmaf(kf + 1.0f, step, excl + l0) * inv_wsum;
    const float c2 = fmaf(kf + 2.0f, step, excl + l1) * inv_wsum;
    const float c3 = fmaf(kf + 3.0f, step, excl + l2) * inv_wsum;
    const float c4 = fmaf(kf + 4.0f, step, excl + l3) * inv_wsum;

    // ---- B. packed interior boundaries (bytes) ----
    const int m1 = __float2int_rd(fmaf(65.0f, c1, 0.5f));
    const int m2 = __float2int_rd(fmaf(65.0f, c2, 0.5f));
    const int m3 = __float2int_rd(fmaf(65.0f, c3, 0.5f));
    const unsigned M = (unsigned)m1 | ((unsigned)m2 << 8) | ((unsigned)m3 << 16);

    // ---- C. stage cdf + bins into the unified table ----
    float4 cv4; cv4.x = c0; cv4.y = c1; cv4.z = c2; cv4.w = c3;
    float4 bv4; bv4.x = b0; bv4.y = b1; bv4.z = b2; bv4.w = b3;
    *reinterpret_cast<float4*>(tb + k)        = cv4;
    *reinterpret_cast<float4*>(tb + BOFF + k) = bv4;
    if (lane == 31) {
        tb[128]        = c4;
        tb[BOFF + 128] = __ldg(ebrow + 128);
    }
    __syncwarp(FULL);

    const float dfn = farv - nearv;
    float* orow = out + ray * 65u;

    // ---- D. dual interleaved ladder over chunk tops ----
    const float u0 = ((float)lane + 0.5f)  * INV_NB;
    const float u1 = ((float)lane + 32.5f) * INV_NB;

    int p0 = 0, p1 = 0;
    {
        const float cs = __shfl_sync(FULL, c0, 16);
        if (cs <= u0) p0 = 16;
        if (cs <= u1) p1 = 16;
    }
    #pragma unroll
    for (int st = 8; st >= 1; st >>= 1) {
        const float a0 = __shfl_sync(FULL, c0, p0 + st);
        const float a1 = __shfl_sync(FULL, c0, p1 + st);
        if (a0 <= u0) p0 += st;
        if (a1 <= u1) p1 += st;
    }

    // ---- E. SWAR sub-segment select ----
    const unsigned M0 = __shfl_sync(FULL, M, p0);
    const unsigned M1 = __shfl_sync(FULL, M, p1);
    const unsigned J0 = (unsigned)lane        * 0x01010101u;
    const unsigned J1 = (unsigned)(lane + 32) * 0x01010101u;
    const int r0 = __popc(((J0 | 0x80808080u) - M0) & 0x00808080u);
    const int r1 = __popc(((J1 | 0x80808080u) - M1) & 0x00808080u);

    const int i0 = p0 * 4 + r0;
    const int i1 = p1 * 4 + r1;

    // one base pointer each; compiler folds the rest into LDS immediates
    const float* e0 = tb + i0;
    const float* e1 = tb + i1;
    const float clo0 = e0[0], chi0 = e0[1], blo0 = e0[BOFF], bhi0 = e0[BOFF + 1];
    const float clo1 = e1[0], chi1 = e1[1], blo1 = e1[BOFF], bhi1 = e1[BOFF + 1];

    const float t0  = (u0 - clo0) * __fdividef(1.0f, chi0 - clo0);
    const float t1  = (u1 - clo1) * __fdividef(1.0f, chi1 - clo1);
    const float bb0 = fmaf(t0, bhi0 - blo0, blo0);
    const float bb1 = fmaf(t1, bhi1 - blo1, blo1);
    orow[lane]      = fmaf(bb0, dfn, nearv);
    orow[lane + 32] = fmaf(bb1, dfn, nearv);

    // ---- F. j = 64: owner lane computes locally (no extra shfl) ----
    {
        const float u = 64.5f * INV_NB;
        const unsigned msk = __ballot_sync(FULL, c0 <= u);   // lane0 always set
        const int pt = 31 - __clz(msk);
        if (lane == pt) {
            const unsigned Jt = 64u * 0x01010101u;
            const int rt = __popc(((Jt | 0x80808080u) - M) & 0x00808080u);
            const float* et = tb + (lane * 4 + rt);
            const float clo = et[0], chi = et[1];
            const float blo = et[BOFF], bhi = et[BOFF + 1];
            const float t  = (u - clo) * __fdividef(1.0f, chi - clo);
            const float bb = fmaf(t, bhi - blo, blo);
            orow[64] = fmaf(bb, dfn, nearv);
        }
    }
}

extern "C" void kernel_launch(void* const* d_in, const int* in_sizes, int n_in,
                              void* d_out, int out_size) {
    const float* weights = (const float*)d_in[0];
    const float* ebins   = (const float*)d_in[1];
    const float* nears   = (const float*)d_in[2];
    const float* fars    = (const float*)d_in[3];
    float* out = (float*)d_out;

    const int R = in_sizes[2];  // nears has R elements
    const int grid = (R + WPB - 1) / WPB;
    neus_sampler_kernel<<<grid, NTHREADS>>>(weights, ebins, nears, fars, out, R);
}

// round 16
// speedup vs baseline: 1.1232x; 1.1232x over previous
#include <cuda_runtime.h>
#include <cuda_bf16.h>

// NeuSSampler inverse-CDF importance sampling — v16: v12 minus warp-wide
// overhead. weights [R,128,1] f32, existing_bins [R,129] f32, nears [R,1],
// fars [R,1] -> out [R,65] f32.  One warp per ray.
//
// Validated fetch split: owner chunk via dual 5-probe shfl ladder (shared
// first probe), sub-segment via SWAR byte-compare, cdf endpoints via scalar
// LDS, bin endpoints via LDG on the prefetched L1-resident ebins row.
// j=64 handled entirely locally by its owner lane (exactly one lane has
// c0 <= u64 < c4, since c4[L] is arithmetically identical to c0[L+1]).

#define S_SAMP 128
#define NB 65
#define HIST_PAD 1e-5f
#define EPS_V 1e-5f
#define WPB 8
#define NTHREADS (WPB * 32)
#define INV_NB (1.0f / 65.0f)
#define FULL 0xffffffffu

__global__ __launch_bounds__(NTHREADS)
void neus_sampler_kernel(const float* __restrict__ weights,
                         const float* __restrict__ ebins,
                         const float* __restrict__ nears,
                         const float* __restrict__ fars,
                         float* __restrict__ out,
                         int R)
{
    __shared__ __align__(16) float cdf_sm[WPB][132];

    const int warp = threadIdx.x >> 5;
    const int lane = threadIdx.x & 31;
    const unsigned ray = blockIdx.x * WPB + warp;
    if (ray >= (unsigned)R) return;

    // ---- A0. start global traffic early (32-bit offsets) ----
    const int k = lane * 4;
    const float* ebrow = ebins + ray * 129u;
    if (lane < 5) {  // warm the whole 516B row into L1
        asm volatile("prefetch.global.L1 [%0];" :: "l"(ebrow + lane * 32));
    }
    const float4 wv = *reinterpret_cast<const float4*>(weights + ray * 128u + k);
    const float nearv = __ldg(nears + ray);
    const float farv  = __ldg(fars + ray);

    const float l0 = wv.x;
    const float l1 = l0 + wv.y;
    const float l2 = l1 + wv.z;
    const float l3 = l2 + wv.w;

    // ---- A1. warp inclusive scan over chunk sums ----
    float pre = l3;
    #pragma unroll
    for (int off = 1; off < 32; off <<= 1) {
        float v = __shfl_up_sync(FULL, pre, off);
        if (lane >= off) pre += v;
    }
    const float total_raw = __shfl_sync(FULL, pre, 31);
    const float excl      = pre - l3;

    const float total_wp = total_raw + (float)S_SAMP * HIST_PAD;
    const float padding  = fmaxf(0.0f, EPS_V - total_wp);
    const float inv_wsum = __fdividef(1.0f, total_wp + padding);
    const float step     = HIST_PAD + padding * (1.0f / (float)S_SAMP);

    const float kf = (float)k;
    const float c0 = fmaf(kf,        step, excl     ) * inv_wsum;
    const float c1 = fmaf(kf + 1.0f, step, excl + l0) * inv_wsum;
    const float c2 = fmaf(kf + 2.0f, step, excl + l1) * inv_wsum;
    const float c3 = fmaf(kf + 3.0f, step, excl + l2) * inv_wsum;
    const float c4 = fmaf(kf + 4.0f, step, excl + l3) * inv_wsum;

    // ---- B. packed interior boundaries (bytes) ----
    const int m1 = __float2int_rd(fmaf(65.0f, c1, 0.5f));
    const int m2 = __float2int_rd(fmaf(65.0f, c2, 0.5f));
    const int m3 = __float2int_rd(fmaf(65.0f, c3, 0.5f));
    const unsigned M = (unsigned)m1 | ((unsigned)m2 << 8) | ((unsigned)m3 << 16);

    // ---- C. cdf-only smem table ----
    float* cw = cdf_sm[warp];
    float4 cv4; cv4.x = c0; cv4.y = c1; cv4.z = c2; cv4.w = c3;
    *reinterpret_cast<float4*>(cw + k) = cv4;
    if (lane == 31) cw[128] = c4;
    __syncwarp(FULL);

    const float dfn = farv - nearv;
    float* orow = out + ray * 65u;

    // ---- D. dual interleaved ladder over chunk tops ----
    const float u0 = ((float)lane + 0.5f)  * INV_NB;
    const float u1 = ((float)lane + 32.5f) * INV_NB;

    int p0 = 0, p1 = 0;
    {
        const float cs = __shfl_sync(FULL, c0, 16);
        if (cs <= u0) p0 = 16;
        if (cs <= u1) p1 = 16;
    }
    #pragma unroll
    for (int st = 8; st >= 1; st >>= 1) {
        const float a0 = __shfl_sync(FULL, c0, p0 + st);
        const float a1 = __shfl_sync(FULL, c0, p1 + st);
        if (a0 <= u0) p0 += st;
        if (a1 <= u1) p1 += st;
    }

    // ---- E. SWAR sub-segment select ----
    const unsigned M0 = __shfl_sync(FULL, M, p0);
    const unsigned M1 = __shfl_sync(FULL, M, p1);
    const unsigned J0 = (unsigned)lane        * 0x01010101u;
    const unsigned J1 = (unsigned)(lane + 32) * 0x01010101u;
    const int r0 = __popc(((J0 | 0x80808080u) - M0) & 0x00808080u);
    const int r1 = __popc(((J1 | 0x80808080u) - M1) & 0x00808080u);

    const int i0 = p0 * 4 + r0;
    const int i1 = p1 * 4 + r1;

    // cdf endpoints: scalar LDS; bin endpoints: L1-hit LDG
    const float clo0 = cw[i0], chi0 = cw[i0 + 1];
    const float clo1 = cw[i1], chi1 = cw[i1 + 1];
    const float blo0 = __ldg(ebrow + i0);
    const float bhi0 = __ldg(ebrow + i0 + 1);
    const float blo1 = __ldg(ebrow + i1);
    const float bhi1 = __ldg(ebrow + i1 + 1);

    const float t0  = (u0 - clo0) * __fdividef(1.0f, chi0 - clo0);
    const float t1  = (u1 - clo1) * __fdividef(1.0f, chi1 - clo1);
    const float bb0 = fmaf(t0, bhi0 - blo0, blo0);
    const float bb1 = fmaf(t1, bhi1 - blo1, blo1);
    orow[lane]      = fmaf(bb0, dfn, nearv);
    orow[lane + 32] = fmaf(bb1, dfn, nearv);

    // ---- F. j = 64: unique owner lane detects itself locally ----
    {
        const float u = 64.5f * INV_NB;
        if (c0 <= u && u < c4) {     // exactly one lane (c4[L] == c0[L+1])
            const unsigned Jt = 64u * 0x01010101u;
            const int rt = __popc(((Jt | 0x80808080u) - M) & 0x00808080u);
            const int it = k + rt;
            const float clo = cw[it], chi = cw[it + 1];
            const float blo = __ldg(ebrow + it);
            const float bhi = __ldg(ebrow + it + 1);
            const float t  = (u - clo) * __fdividef(1.0f, chi - clo);
            const float bb = fmaf(t, bhi - blo, blo);
            orow[64] = fmaf(bb, dfn, nearv);
        }
    }
}

extern "C" void kernel_launch(void* const* d_in, const int* in_sizes, int n_in,
                              void* d_out, int out_size) {
    const float* weights = (const float*)d_in[0];
    const float* ebins   = (const float*)d_in[1];
    const float* nears   = (const float*)d_in[2];
    const float* fars    = (const float*)d_in[3];
    float* out = (float*)d_out;

    const int R = in_sizes[2];  // nears has R elements
    const int grid = (R + WPB - 1) / WPB;
    neus_sampler_kernel<<<grid, NTHREADS>>>(weights, ebins, nears, fars, out, R);
}